// round 12
// baseline (speedup 1.0000x reference)
#include <cuda_runtime.h>
#include <cuda_fp16.h>
#include <math.h>
#include <stdint.h>

#define N_NODES 140000
#define N_EDGES 2240000
#define NFEAT   128
#define NHID    128
#define N_FRAMES 14

// Scratch (allocation-free rule: device globals)
__device__ __half g_supp[(size_t)N_NODES * NHID];   // x@W in fp16 (35.8 MB, L2-resident)
__device__ __half g_wprep[NHID * NFEAT];            // W transposed: [n][k] fp16
__device__ int    g_rowptr[N_NODES + 1];

// ---------------------------------------------------------------------------
// fp16 m16n8k16 mma (fp32 accum)
// ---------------------------------------------------------------------------
__device__ __forceinline__ void mma_fp16(float* c, const uint32_t* a,
                                         uint32_t b0, uint32_t b1)
{
    asm volatile(
        "mma.sync.aligned.m16n8k16.row.col.f32.f16.f16.f32 "
        "{%0,%1,%2,%3}, {%4,%5,%6,%7}, {%8,%9}, {%0,%1,%2,%3};\n"
        : "+f"(c[0]), "+f"(c[1]), "+f"(c[2]), "+f"(c[3])
        : "r"(a[0]), "r"(a[1]), "r"(a[2]), "r"(a[3]), "r"(b0), "r"(b1));
}

// ---------------------------------------------------------------------------
// Kernel 0: W (fp32 [k][n]) -> g_wprep fp16 [n][k]
// ---------------------------------------------------------------------------
__global__ void prep_w(const float* __restrict__ W)
{
    const int k = blockIdx.x;     // 0..127
    const int n = threadIdx.x;    // 0..127
    g_wprep[n * NFEAT + k] = __float2half_rn(W[k * NHID + n]);
}

// ---------------------------------------------------------------------------
// Kernel 1: CSR row_ptr via binary search on sorted edge_row
// ---------------------------------------------------------------------------
__global__ void rowptr_kernel(const int* __restrict__ erow, int nnodes, int nedges)
{
    int n = blockIdx.x * blockDim.x + threadIdx.x;
    if (n > nnodes) return;
    int lo = 0, hi = nedges;
    while (lo < hi) {
        int mid = (lo + hi) >> 1;
        if (erow[mid] < n) lo = mid + 1;
        else hi = mid;
    }
    g_rowptr[n] = lo;
}

// ---------------------------------------------------------------------------
// Kernel 2: support = x @ W, single-pass fp16 m16n8k16, fp32 accum.
// 8 warps, 128x128 tile, warp = 32 rows x 64 cols.
// ---------------------------------------------------------------------------
__global__ __launch_bounds__(256)
void gemm_fp16(const float* __restrict__ x, int nrows)
{
    __shared__ union {
        struct { __half X[128][72]; __half W[128][72]; } s;
        __half O[128][136];
    } sh;

    const int tid  = threadIdx.x;
    const int lane = tid & 31;
    const int w    = tid >> 5;
    const int g    = lane >> 2;
    const int tg   = lane & 3;
    const int rbase = (w & 3) * 32;
    const int cbase = (w >> 2) * 64;
    const int m0   = blockIdx.x * 128;

    float acc0[8][4], acc1[8][4];
#pragma unroll
    for (int nt = 0; nt < 8; ++nt)
#pragma unroll
        for (int i = 0; i < 4; ++i) { acc0[nt][i] = 0.f; acc1[nt][i] = 0.f; }

    for (int ks = 0; ks < 128; ks += 64) {
#pragma unroll
        for (int t = 0; t < 8; ++t) {
            int i  = tid + t * 256;
            int r  = i >> 4;
            int c4 = (i & 15) * 4;
            int gr = m0 + r;
            float4 v = make_float4(0.f, 0.f, 0.f, 0.f);
            if (gr < nrows) v = *(const float4*)&x[(size_t)gr * NFEAT + ks + c4];
            __half2 p0 = __floats2half2_rn(v.x, v.y);
            __half2 p1 = __floats2half2_rn(v.z, v.w);
            *(uint2*)&sh.s.X[r][c4] = make_uint2(*(uint32_t*)&p0, *(uint32_t*)&p1);
        }
#pragma unroll
        for (int t = 0; t < 4; ++t) {
            int i = tid + t * 256;
            int n = i >> 3;
            int q = i & 7;
            *(uint4*)&sh.s.W[n][q * 8] =
                *(const uint4*)(g_wprep + n * NFEAT + ks + q * 8);
        }
        __syncthreads();

#pragma unroll
        for (int kk = 0; kk < 64; kk += 16) {
            const int ka = kk + tg * 2;
            uint32_t a0[4], a1[4];
            a0[0] = *(uint32_t*)&sh.s.X[rbase + g     ][ka];
            a0[1] = *(uint32_t*)&sh.s.X[rbase + g + 8 ][ka];
            a0[2] = *(uint32_t*)&sh.s.X[rbase + g     ][ka + 8];
            a0[3] = *(uint32_t*)&sh.s.X[rbase + g + 8 ][ka + 8];
            a1[0] = *(uint32_t*)&sh.s.X[rbase + g + 16][ka];
            a1[1] = *(uint32_t*)&sh.s.X[rbase + g + 24][ka];
            a1[2] = *(uint32_t*)&sh.s.X[rbase + g + 16][ka + 8];
            a1[3] = *(uint32_t*)&sh.s.X[rbase + g + 24][ka + 8];

#pragma unroll
            for (int nt = 0; nt < 8; ++nt) {
                const int nc = cbase + nt * 8 + g;
                uint32_t b0 = *(uint32_t*)&sh.s.W[nc][ka];
                uint32_t b1 = *(uint32_t*)&sh.s.W[nc][ka + 8];
                mma_fp16(acc0[nt], a0, b0, b1);
                mma_fp16(acc1[nt], a1, b0, b1);
            }
        }
        __syncthreads();
    }

#pragma unroll
    for (int nt = 0; nt < 8; ++nt) {
        int col = cbase + nt * 8 + tg * 2;
        *(__half2*)&sh.O[rbase + g     ][col] = __floats2half2_rn(acc0[nt][0], acc0[nt][1]);
        *(__half2*)&sh.O[rbase + g + 8 ][col] = __floats2half2_rn(acc0[nt][2], acc0[nt][3]);
        *(__half2*)&sh.O[rbase + g + 16][col] = __floats2half2_rn(acc1[nt][0], acc1[nt][1]);
        *(__half2*)&sh.O[rbase + g + 24][col] = __floats2half2_rn(acc1[nt][2], acc1[nt][3]);
    }
    __syncthreads();
#pragma unroll
    for (int t = 0; t < 8; ++t) {
        int i  = tid + t * 256;
        int r  = i >> 4;
        int c8 = (i & 15) * 8;
        if ((m0 + r) < nrows)
            *(uint4*)&g_supp[(size_t)(m0 + r) * NHID + c8] = *(uint4*)&sh.O[r][c8];
    }
}

// ---------------------------------------------------------------------------
// Kernel 3: FUSED SpMM + bias + relu + frame-max + log_softmax.
// Warp per output row g. 16 lanes per edge (uint4 = 8 feats/lane);
// half-warp 0 takes even edges, half-warp 1 odd edges (parallel pair).
// Edge idx/val batch-loaded coalesced, shfl-broadcast with per-lane src.
// ---------------------------------------------------------------------------
__device__ __forceinline__ void gather_fma(float* acc, const char* base,
                                           int c, float v)
{
    uint4 q = *(const uint4*)(base + (size_t)c * (NHID * 2));
    float2 t0 = __half22float2(*(__half2*)&q.x);
    float2 t1 = __half22float2(*(__half2*)&q.y);
    float2 t2 = __half22float2(*(__half2*)&q.z);
    float2 t3 = __half22float2(*(__half2*)&q.w);
    acc[0] = fmaf(v, t0.x, acc[0]); acc[1] = fmaf(v, t0.y, acc[1]);
    acc[2] = fmaf(v, t1.x, acc[2]); acc[3] = fmaf(v, t1.y, acc[3]);
    acc[4] = fmaf(v, t2.x, acc[4]); acc[5] = fmaf(v, t2.y, acc[5]);
    acc[6] = fmaf(v, t3.x, acc[6]); acc[7] = fmaf(v, t3.y, acc[7]);
}

__global__ __launch_bounds__(256)
void spmm_head(const float* __restrict__ bias, const float* __restrict__ eval,
               const int* __restrict__ ecol, float* __restrict__ out, int ng)
{
    const int g    = blockIdx.x * 8 + (threadIdx.x >> 5);
    const int lane = threadIdx.x & 31;
    if (g >= ng) return;
    const int hl  = lane & 15;          // feature lane 0..15
    const int fo  = hl * 8;             // first of 8 owned features
    const int sel = lane >> 4;          // 0: even edges, 1: odd edges

    float bb[8];
    *(float4*)&bb[0] = *(const float4*)&bias[fo];
    *(float4*)&bb[4] = *(const float4*)&bias[fo + 4];

    const char* supp_base = (const char*)g_supp + (size_t)fo * 2;

    float vm[8];
#pragma unroll
    for (int i = 0; i < 8; ++i) vm[i] = -INFINITY;

    for (int f = 0; f < N_FRAMES; ++f) {
        const int node = f * ng + g;
        const int s = g_rowptr[node];
        const int e = g_rowptr[node + 1];

        float acc[8];
#pragma unroll
        for (int i = 0; i < 8; ++i) acc[i] = 0.f;

        for (int base = s; base < e; base += 32) {
            const int idx = base + lane;
            int   cl = 0;
            float vl = 0.f;
            if (idx < e) {
                cl = __ldcs(&ecol[idx]);
                vl = __ldcs(&eval[idx]);
            }
            const int m = min(32, e - base);
            int k = 0;
            // 4 pairs (8 edges) per iteration; this half-warp handles k+sel
            for (; k + 8 <= m; k += 8) {
                int   c0 = __shfl_sync(0xffffffffu, cl, k     + sel);
                int   c1 = __shfl_sync(0xffffffffu, cl, k + 2 + sel);
                int   c2 = __shfl_sync(0xffffffffu, cl, k + 4 + sel);
                int   c3 = __shfl_sync(0xffffffffu, cl, k + 6 + sel);
                float v0 = __shfl_sync(0xffffffffu, vl, k     + sel);
                float v1 = __shfl_sync(0xffffffffu, vl, k + 2 + sel);
                float v2 = __shfl_sync(0xffffffffu, vl, k + 4 + sel);
                float v3 = __shfl_sync(0xffffffffu, vl, k + 6 + sel);
                gather_fma(acc, supp_base, c0, v0);
                gather_fma(acc, supp_base, c1, v1);
                gather_fma(acc, supp_base, c2, v2);
                gather_fma(acc, supp_base, c3, v3);
            }
            for (; k < m; k += 2) {
                // odd-m tail: slot k+1 has vl=0 loaded -> zero contribution
                int   c = __shfl_sync(0xffffffffu, cl, k + sel);
                float v = __shfl_sync(0xffffffffu, vl, k + sel);
                gather_fma(acc, supp_base, c, v);
            }
        }

        // combine even/odd halves (symmetric: both halves end with full sum)
#pragma unroll
        for (int i = 0; i < 8; ++i)
            acc[i] += __shfl_xor_sync(0xffffffffu, acc[i], 16);

#pragma unroll
        for (int i = 0; i < 8; ++i)
            vm[i] = fmaxf(vm[i], fmaxf(acc[i] + bb[i], 0.f));
    }

    // log_softmax over 128 features (16 feature-lanes; halves are duplicates)
    float m = vm[0];
#pragma unroll
    for (int i = 1; i < 8; ++i) m = fmaxf(m, vm[i]);
#pragma unroll
    for (int o = 8; o; o >>= 1) m = fmaxf(m, __shfl_xor_sync(0xffffffffu, m, o));

    float s = 0.f;
#pragma unroll
    for (int i = 0; i < 8; ++i) s += expf(vm[i] - m);
#pragma unroll
    for (int o = 8; o; o >>= 1) s += __shfl_xor_sync(0xffffffffu, s, o);

    float ls = m + logf(s);
    if (sel == 0) {
        float4 r0 = make_float4(vm[0] - ls, vm[1] - ls, vm[2] - ls, vm[3] - ls);
        float4 r1 = make_float4(vm[4] - ls, vm[5] - ls, vm[6] - ls, vm[7] - ls);
        *(float4*)&out[(size_t)g * NHID + fo]     = r0;
        *(float4*)&out[(size_t)g * NHID + fo + 4] = r1;
    }
}

// ---------------------------------------------------------------------------
extern "C" void kernel_launch(void* const* d_in, const int* in_sizes, int n_in,
                              void* d_out, int out_size)
{
    const float* x    = (const float*)d_in[0];
    const float* W    = (const float*)d_in[1];
    const float* b    = (const float*)d_in[2];
    const float* evl  = (const float*)d_in[3];
    const int*   erow = (const int*)  d_in[4];
    const int*   ecol = (const int*)  d_in[5];
    float* out = (float*)d_out;

    const int N  = in_sizes[0] / NFEAT;   // 140000
    const int E  = in_sizes[3];           // 2240000
    const int NG = N / N_FRAMES;          // 10000

    prep_w<<<128, 128>>>(W);
    rowptr_kernel<<<(N + 1 + 255) / 256, 256>>>(erow, N, E);
    gemm_fp16<<<(N + 127) / 128, 256>>>(x, N);
    spmm_head<<<(NG + 7) / 8, 256>>>(b, evl, ecol, out, NG);
}